// round 1
// baseline (speedup 1.0000x reference)
#include <cuda_runtime.h>
#include <mma.h>
#include <cstdint>

using namespace nvcuda;

#define NB      256
#define NCOLS   512
#define NNODE   256
#define VOCAB   100
#define DH      128
#define NTOT    (2*NB*NNODE)      /* 131072 nodes */
#define EINT    (NTOT*8)          /* 1048576 edges */
#define MERGED  (NB*NNODE)        /* 65536 */
#define LN_EPSF 1e-5f

// ---------------- scratch (device globals; no allocation allowed) -----------
__device__ float g_h[(size_t)NTOT * DH];   // node features
__device__ float g_z[(size_t)NTOT * DH];   // (1+eps)*h + agg
__device__ float g_t[(size_t)NTOT * DH];   // MLP hidden
__device__ float g_tab[38 * DH];           // los_table @ ew + eb (per layer)

__device__ __forceinline__ void red_add_v4(float* p, float4 v) {
    asm volatile("red.global.add.v4.f32 [%0], {%1,%2,%3,%4};"
                 :: "l"(p), "f"(v.x), "f"(v.y), "f"(v.z), "f"(v.w) : "memory");
}

// ---------------- embedding gather ------------------------------------------
// h[n][:] = emb_table[c, x[b,c], :]  with c = n & 511, b = n >> 9
__global__ void embed_k(const int* __restrict__ x, const float* __restrict__ emb) {
    int tid = blockIdx.x * blockDim.x + threadIdx.x;
    int n = tid >> 5, l = tid & 31;
    if (n >= NTOT) return;
    int c = n & (NCOLS - 1);
    int b = n >> 9;
    int v = __ldg(&x[b * NCOLS + c]);
    float4 val = __ldg(reinterpret_cast<const float4*>(emb + ((size_t)c * VOCAB + v) * DH) + l);
    reinterpret_cast<float4*>(g_h + (size_t)n * DH)[l] = val;
}

// ---------------- z = (1+eps) * h --------------------------------------------
__global__ void selfinit_k(const float* __restrict__ epsp) {
    float s = 1.0f + __ldg(epsp);
    size_t i = (size_t)blockIdx.x * blockDim.x + threadIdx.x;
    float4 v = reinterpret_cast<const float4*>(g_h)[i];
    v.x *= s; v.y *= s; v.z *= s; v.w *= s;
    reinterpret_cast<float4*>(g_z)[i] = v;
}

// ---------------- plain GIN scatter: z[dst] += h[src] ------------------------
__global__ void scatter1_k(const int* __restrict__ src, const int* __restrict__ dst) {
    int tid = blockIdx.x * 256 + threadIdx.x;
    int e = tid >> 5, l = tid & 31;
    if (e >= EINT) return;
    int s = __ldg(&src[e]);
    int d = __ldg(&dst[e]);
    float4 v = __ldg(reinterpret_cast<const float4*>(g_h + (size_t)s * DH) + l);
    red_add_v4(g_z + (size_t)d * DH + (l << 2), v);
}

// ---------------- GINE scatter (original edges): z[dst] += relu(h[src]+tab[0])
__global__ void scatter2a_k(const int* __restrict__ src, const int* __restrict__ dst) {
    int tid = blockIdx.x * 256 + threadIdx.x;
    int e = tid >> 5, l = tid & 31;
    if (e >= EINT) return;
    int s = __ldg(&src[e]);
    int d = __ldg(&dst[e]);
    float4 v = __ldg(reinterpret_cast<const float4*>(g_h + (size_t)s * DH) + l);
    float4 c = *(reinterpret_cast<const float4*>(g_tab) + l);  // row 0
    v.x = fmaxf(v.x + c.x, 0.f);
    v.y = fmaxf(v.y + c.y, 0.f);
    v.z = fmaxf(v.z + c.z, 0.f);
    v.w = fmaxf(v.w + c.w, 0.f);
    red_add_v4(g_z + (size_t)d * DH + (l << 2), v);
}

// ---------------- GINE scatter (extra edges e -> e+MERGED) -------------------
__global__ void scatter2b_k(const int* __restrict__ los) {
    int tid = blockIdx.x * 256 + threadIdx.x;
    int e = tid >> 5, l = tid & 31;
    if (e >= MERGED) return;
    int lo = __ldg(&los[e >> 8]);
    float4 t = *(reinterpret_cast<const float4*>(g_tab + lo * DH) + l);
    float4 v = __ldg(reinterpret_cast<const float4*>(g_h + (size_t)e * DH) + l);
    v.x = fmaxf(v.x + t.x, 0.f);
    v.y = fmaxf(v.y + t.y, 0.f);
    v.z = fmaxf(v.z + t.z, 0.f);
    v.w = fmaxf(v.w + t.w, 0.f);
    red_add_v4(g_z + (size_t)(e + MERGED) * DH + (l << 2), v);
}

// ---------------- tab[r][:] = los_table[r] @ ew + eb --------------------------
__global__ void table_k(const float* __restrict__ lt, const float* __restrict__ ew,
                        const float* __restrict__ eb) {
    int r = blockIdx.x, d = threadIdx.x;
    float acc = __ldg(&eb[d]);
#pragma unroll
    for (int j = 0; j < 8; j++)
        acc += __ldg(&lt[r * 8 + j]) * __ldg(&ew[j * DH + d]);
    g_tab[r * DH + d] = acc;
}

// ---------------- GEMM (tf32 wmma), optional fused bias+LN+relu ---------------
// Out[64 x 128] = A[64 x 128] @ W[128 x 128] (+ bias [+ LayerNorm + relu])
#define GR 64
__global__ __launch_bounds__(256) void gemm_k(
    const float* __restrict__ A, const float* __restrict__ W,
    const float* __restrict__ bias, const float* __restrict__ gam,
    const float* __restrict__ bet, float* __restrict__ Out, int do_ln)
{
    __shared__ float As[GR][136];
    __shared__ float Ws[16][136];
    __shared__ float mus[GR], invs[GR];

    int tid = threadIdx.x;
    int wid = tid >> 5;
    size_t n0 = (size_t)blockIdx.x * GR;

    // load full A tile (64x128)
    {
        const float4* ap = reinterpret_cast<const float4*>(A + n0 * DH);
#pragma unroll
        for (int it = 0; it < 8; it++) {
            int i = tid + it * 256;                  // 0..2047 float4s
            int r = i >> 5, c4 = i & 31;
            float4 v = __ldg(ap + i);
            *reinterpret_cast<float4*>(&As[r][c4 * 4]) = v;
        }
    }

    wmma::fragment<wmma::accumulator, 16, 16, 8, float> acc[4];
#pragma unroll
    for (int t = 0; t < 4; t++) wmma::fill_fragment(acc[t], 0.0f);

    int tr  = wid >> 1;        // tile row 0..3
    int tc0 = (wid & 1) * 4;   // tile col base 0 or 4

    for (int kc = 0; kc < DH; kc += 16) {
        // load W rows [kc, kc+16)
#pragma unroll
        for (int it = 0; it < 2; it++) {
            int i = tid + it * 256;                  // 0..511 float4s
            int r = i >> 5, c4 = i & 31;
            float4 v = __ldg(reinterpret_cast<const float4*>(W + (size_t)(kc + r) * DH) + c4);
            *reinterpret_cast<float4*>(&Ws[r][c4 * 4]) = v;
        }
        __syncthreads();
#pragma unroll
        for (int kk = 0; kk < 16; kk += 8) {
            wmma::fragment<wmma::matrix_a, 16, 16, 8, wmma::precision::tf32, wmma::row_major> af;
            wmma::load_matrix_sync(af, &As[tr * 16][kc + kk], 136);
#pragma unroll
            for (int i = 0; i < af.num_elements; i++) af.x[i] = wmma::__float_to_tf32(af.x[i]);
#pragma unroll
            for (int t = 0; t < 4; t++) {
                wmma::fragment<wmma::matrix_b, 16, 16, 8, wmma::precision::tf32, wmma::row_major> bf;
                wmma::load_matrix_sync(bf, &Ws[kk][(tc0 + t) * 16], 136);
#pragma unroll
                for (int i = 0; i < bf.num_elements; i++) bf.x[i] = wmma::__float_to_tf32(bf.x[i]);
                wmma::mma_sync(acc[t], af, bf, acc[t]);
            }
        }
        __syncthreads();
    }

    // stage C into As (A no longer needed)
#pragma unroll
    for (int t = 0; t < 4; t++)
        wmma::store_matrix_sync(&As[tr * 16][(tc0 + t) * 16], acc[t], 136, wmma::mem_row_major);
    __syncthreads();

    if (do_ln) {
        // stats: 4 threads per row, 32 cols each
        int row = tid >> 2, q = tid & 3;
        float s = 0.f, ss = 0.f;
#pragma unroll
        for (int i = 0; i < 32; i++) {
            int c = q * 32 + i;
            float xv = As[row][c] + __ldg(&bias[c]);
            s += xv; ss += xv * xv;
        }
        s  += __shfl_xor_sync(0xffffffffu, s, 1);
        ss += __shfl_xor_sync(0xffffffffu, ss, 1);
        s  += __shfl_xor_sync(0xffffffffu, s, 2);
        ss += __shfl_xor_sync(0xffffffffu, ss, 2);
        float mu  = s * (1.0f / 128.0f);
        float var = ss * (1.0f / 128.0f) - mu * mu;
        mus[row]  = mu;
        invs[row] = rsqrtf(var + LN_EPSF);
        __syncthreads();
        for (int idx = tid; idx < GR * DH; idx += 256) {
            int r = idx >> 7, c = idx & 127;
            float xv = As[r][c] + __ldg(&bias[c]);
            float y = (xv - mus[r]) * invs[r] * __ldg(&gam[c]) + __ldg(&bet[c]);
            Out[(n0 + r) * DH + c] = fmaxf(y, 0.f);
        }
    } else {
        for (int idx = tid; idx < GR * DH; idx += 256) {
            int r = idx >> 7, c = idx & 127;
            Out[(n0 + r) * DH + c] = As[r][c] + __ldg(&bias[c]);
        }
    }
}

// ---------------- per-graph node sum: out[g, off+d] = sum_j h[g*256+j][d] -----
__global__ void sum_k(float* __restrict__ out, int off) {
    int g = blockIdx.x, d = threadIdx.x;
    const float* base = g_h + (size_t)g * NNODE * DH + d;
    float s = 0.f;
#pragma unroll 8
    for (int j = 0; j < NNODE; j++) s += base[(size_t)j * DH];
    out[g * 256 + off + d] = s;
}

// ---------------- launch ------------------------------------------------------
extern "C" void kernel_launch(void* const* d_in, const int* in_sizes, int n_in,
                              void* d_out, int out_size)
{
    const int*   x     = (const int*)d_in[0];
    const int*   ei    = (const int*)d_in[1];
    const int*   los   = (const int*)d_in[2];
    const float* emb   = (const float*)d_in[3];
    const float* lt    = (const float*)d_in[4];
    const float* g1w1  = (const float*)d_in[5];
    const float* g1b1  = (const float*)d_in[6];
    const float* g1g   = (const float*)d_in[7];
    const float* g1be  = (const float*)d_in[8];
    const float* g1w2  = (const float*)d_in[9];
    const float* g1b2  = (const float*)d_in[10];
    const float* g1eps = (const float*)d_in[11];
    const float* g2w1  = (const float*)d_in[12];
    const float* g2b1  = (const float*)d_in[13];
    const float* g2g   = (const float*)d_in[14];
    const float* g2be  = (const float*)d_in[15];
    const float* g2w2  = (const float*)d_in[16];
    const float* g2b2  = (const float*)d_in[17];
    const float* g2eps = (const float*)d_in[18];
    const float* g2ew  = (const float*)d_in[19];
    const float* g2eb  = (const float*)d_in[20];
    float* out = (float*)d_out;

    const int* src = ei;
    const int* dst = ei + EINT;

    void *ph, *pz, *pt;
    cudaGetSymbolAddress(&ph, g_h);
    cudaGetSymbolAddress(&pz, g_z);
    cudaGetSymbolAddress(&pt, g_t);
    float* hB = (float*)ph;
    float* zB = (float*)pz;
    float* tB = (float*)pt;

    embed_k<<<(NTOT * 32) / 256, 256>>>(x, emb);

    // ---- GIN layer group 1 (2 layers) ----
    for (int i = 0; i < 2; i++) {
        selfinit_k<<<(NTOT * DH / 4) / 256, 256>>>(g1eps + i);
        scatter1_k<<<(EINT * 32) / 256, 256>>>(src, dst);
        gemm_k<<<NTOT / GR, 256>>>(zB, g1w1 + (size_t)i * DH * DH,
                                   g1b1 + i * DH, g1g + i * DH, g1be + i * DH, tB, 1);
        gemm_k<<<NTOT / GR, 256>>>(tB, g1w2 + (size_t)i * DH * DH,
                                   g1b2 + i * DH, nullptr, nullptr, hB, 0);
    }
    sum_k<<<2 * NB, DH>>>(out, 0);          // ad_dis -> out[:, 0:128]

    // ---- GINE layer group 2 (2 layers) ----
    for (int i = 0; i < 2; i++) {
        table_k<<<38, DH>>>(lt, g2ew + (size_t)i * 8 * DH, g2eb + i * DH);
        selfinit_k<<<(NTOT * DH / 4) / 256, 256>>>(g2eps + i);
        scatter2a_k<<<(EINT * 32) / 256, 256>>>(src, dst);
        scatter2b_k<<<(MERGED * 32) / 256, 256>>>(los);
        gemm_k<<<NTOT / GR, 256>>>(zB, g2w1 + (size_t)i * DH * DH,
                                   g2b1 + i * DH, g2g + i * DH, g2be + i * DH, tB, 1);
        gemm_k<<<NTOT / GR, 256>>>(tB, g2w2 + (size_t)i * DH * DH,
                                   g2b2 + i * DH, nullptr, nullptr, hB, 0);
    }
    sum_k<<<2 * NB, DH>>>(out, 128);        // x_sum2 -> out[:, 128:256]
}

// round 2
// speedup vs baseline: 1.3837x; 1.3837x over previous
#include <cuda_runtime.h>
#include <mma.h>
#include <cstdint>

using namespace nvcuda;

#define NB      256
#define NCOLS   512
#define NNODE   256
#define VOCAB   100
#define DH      128
#define NTOT    (2*NB*NNODE)      /* 131072 nodes */
#define EINT    (NTOT*8)          /* 1048576 edges */
#define MERGED  (NB*NNODE)        /* 65536 */
#define LN_EPSF 1e-5f

// ---------------- scratch (device globals; no allocation allowed) -----------
__device__ float g_h[(size_t)NTOT * DH];   // node features
__device__ float g_z[(size_t)NTOT * DH];   // (1+eps)*h + agg
__device__ float g_tab[38 * DH];           // los_table @ ew + eb (per layer)
__device__ int   g_cnt[NTOT];              // in-degree
__device__ int   g_off[NTOT];              // CSR offsets (exclusive)
__device__ int   g_cur[NTOT];              // fill cursors
__device__ int   g_eid[EINT];              // src ids grouped by dst
__device__ int   g_part[512];              // scan partials

// ---------------- embedding gather ------------------------------------------
__global__ void embed_k(const int* __restrict__ x, const float* __restrict__ emb) {
    int tid = blockIdx.x * blockDim.x + threadIdx.x;
    int n = tid >> 5, l = tid & 31;
    if (n >= NTOT) return;
    int c = n & (NCOLS - 1);
    int b = n >> 9;
    int v = __ldg(&x[b * NCOLS + c]);
    float4 val = __ldg(reinterpret_cast<const float4*>(emb + ((size_t)c * VOCAB + v) * DH) + l);
    reinterpret_cast<float4*>(g_h + (size_t)n * DH)[l] = val;
}

// ---------------- CSR build ---------------------------------------------------
__global__ void hist_k(const int* __restrict__ dst) {
    int e = blockIdx.x * 256 + threadIdx.x;
    if (e < EINT) atomicAdd(&g_cnt[__ldg(&dst[e])], 1);
}

// block-level inclusive scan of 256 counts; write block total
__global__ void scanA_k() {
    __shared__ int s[256];
    int t = threadIdx.x;
    int i = blockIdx.x * 256 + t;
    int c = g_cnt[i];
    s[t] = c;
    __syncthreads();
#pragma unroll
    for (int o = 1; o < 256; o <<= 1) {
        int v = (t >= o) ? s[t - o] : 0;
        __syncthreads();
        s[t] += v;
        __syncthreads();
    }
    g_off[i] = s[t];                       // inclusive, local
    if (t == 255) g_part[blockIdx.x] = s[255];
}

// exclusive scan of 512 partials
__global__ void scanB_k() {
    __shared__ int s[512];
    int t = threadIdx.x;
    int c = g_part[t];
    s[t] = c;
    __syncthreads();
#pragma unroll
    for (int o = 1; o < 512; o <<= 1) {
        int v = (t >= o) ? s[t - o] : 0;
        __syncthreads();
        s[t] += v;
        __syncthreads();
    }
    g_part[t] = s[t] - c;                  // exclusive
}

__global__ void scanC_k() {
    int i = blockIdx.x * 256 + threadIdx.x;
    int off = g_off[i] - g_cnt[i] + g_part[blockIdx.x];  // exclusive global
    g_off[i] = off;
    g_cur[i] = off;
}

__global__ void fill_k(const int* __restrict__ src, const int* __restrict__ dst) {
    int e = blockIdx.x * 256 + threadIdx.x;
    if (e >= EINT) return;
    int d = __ldg(&dst[e]);
    int p = atomicAdd(&g_cur[d], 1);
    g_eid[p] = __ldg(&src[e]);
}

// ---------------- GIN aggregation: z[n] = (1+eps)*h[n] + sum h[src] ----------
__global__ void agg1_k(const float* __restrict__ epsp) {
    int tid = blockIdx.x * 256 + threadIdx.x;
    int n = tid >> 5, l = tid & 31;
    float s = 1.0f + __ldg(epsp);
    const float4* h4 = reinterpret_cast<const float4*>(g_h);
    float4 a = h4[(size_t)n * 32 + l];
    float4 acc = make_float4(a.x * s, a.y * s, a.z * s, a.w * s);
    int off = g_off[n], deg = g_cnt[n];
    int k = 0;
    for (; k + 4 <= deg; k += 4) {
        int e0 = g_eid[off + k], e1 = g_eid[off + k + 1];
        int e2 = g_eid[off + k + 2], e3 = g_eid[off + k + 3];
        float4 v0 = __ldg(&h4[(size_t)e0 * 32 + l]);
        float4 v1 = __ldg(&h4[(size_t)e1 * 32 + l]);
        float4 v2 = __ldg(&h4[(size_t)e2 * 32 + l]);
        float4 v3 = __ldg(&h4[(size_t)e3 * 32 + l]);
        acc.x += v0.x + v1.x + v2.x + v3.x;
        acc.y += v0.y + v1.y + v2.y + v3.y;
        acc.z += v0.z + v1.z + v2.z + v3.z;
        acc.w += v0.w + v1.w + v2.w + v3.w;
    }
    for (; k < deg; k++) {
        int e0 = g_eid[off + k];
        float4 v = __ldg(&h4[(size_t)e0 * 32 + l]);
        acc.x += v.x; acc.y += v.y; acc.z += v.z; acc.w += v.w;
    }
    reinterpret_cast<float4*>(g_z)[(size_t)n * 32 + l] = acc;
}

// ---------------- GINE aggregation -------------------------------------------
__global__ void agg2_k(const float* __restrict__ epsp, const int* __restrict__ los) {
    int tid = blockIdx.x * 256 + threadIdx.x;
    int n = tid >> 5, l = tid & 31;
    float s = 1.0f + __ldg(epsp);
    const float4* h4 = reinterpret_cast<const float4*>(g_h);
    const float4* t4 = reinterpret_cast<const float4*>(g_tab);
    float4 c0 = t4[l];                     // tab row 0 (original edges)
    float4 a = h4[(size_t)n * 32 + l];
    float4 acc = make_float4(a.x * s, a.y * s, a.z * s, a.w * s);
    int off = g_off[n], deg = g_cnt[n];
    int k = 0;
    for (; k + 4 <= deg; k += 4) {
        int e0 = g_eid[off + k], e1 = g_eid[off + k + 1];
        int e2 = g_eid[off + k + 2], e3 = g_eid[off + k + 3];
        float4 v0 = __ldg(&h4[(size_t)e0 * 32 + l]);
        float4 v1 = __ldg(&h4[(size_t)e1 * 32 + l]);
        float4 v2 = __ldg(&h4[(size_t)e2 * 32 + l]);
        float4 v3 = __ldg(&h4[(size_t)e3 * 32 + l]);
        acc.x += fmaxf(v0.x + c0.x, 0.f) + fmaxf(v1.x + c0.x, 0.f) + fmaxf(v2.x + c0.x, 0.f) + fmaxf(v3.x + c0.x, 0.f);
        acc.y += fmaxf(v0.y + c0.y, 0.f) + fmaxf(v1.y + c0.y, 0.f) + fmaxf(v2.y + c0.y, 0.f) + fmaxf(v3.y + c0.y, 0.f);
        acc.z += fmaxf(v0.z + c0.z, 0.f) + fmaxf(v1.z + c0.z, 0.f) + fmaxf(v2.z + c0.z, 0.f) + fmaxf(v3.z + c0.z, 0.f);
        acc.w += fmaxf(v0.w + c0.w, 0.f) + fmaxf(v1.w + c0.w, 0.f) + fmaxf(v2.w + c0.w, 0.f) + fmaxf(v3.w + c0.w, 0.f);
    }
    for (; k < deg; k++) {
        int e0 = g_eid[off + k];
        float4 v = __ldg(&h4[(size_t)e0 * 32 + l]);
        acc.x += fmaxf(v.x + c0.x, 0.f);
        acc.y += fmaxf(v.y + c0.y, 0.f);
        acc.z += fmaxf(v.z + c0.z, 0.f);
        acc.w += fmaxf(v.w + c0.w, 0.f);
    }
    if (n >= MERGED) {                     // extra self-cross edge
        int m = n - MERGED;
        int lo = __ldg(&los[m >> 8]);
        float4 t = t4[lo * 32 + l];
        float4 v = h4[(size_t)m * 32 + l];
        acc.x += fmaxf(v.x + t.x, 0.f);
        acc.y += fmaxf(v.y + t.y, 0.f);
        acc.z += fmaxf(v.z + t.z, 0.f);
        acc.w += fmaxf(v.w + t.w, 0.f);
    }
    reinterpret_cast<float4*>(g_z)[(size_t)n * 32 + l] = acc;
}

// ---------------- tab[r][:] = los_table[r] @ ew + eb --------------------------
__global__ void table_k(const float* __restrict__ lt, const float* __restrict__ ew,
                        const float* __restrict__ eb) {
    int r = blockIdx.x, d = threadIdx.x;
    float acc = __ldg(&eb[d]);
#pragma unroll
    for (int j = 0; j < 8; j++)
        acc += __ldg(&lt[r * 8 + j]) * __ldg(&ew[j * DH + d]);
    g_tab[r * DH + d] = acc;
}

// ---------------- fused MLP: Out = relu(LN(A@W1+b1))@W2 + b2 ------------------
#define AS_STRIDE 132
#define AS_OFF 0
#define WS_OFF (128*AS_STRIDE)
#define P_OFF  (2*128*AS_STRIDE)
#define MLP_SMEM_BYTES ((P_OFF + 6*128) * 4)

__device__ __forceinline__ void do_gemm(
    const float* __restrict__ As, const float* __restrict__ Ws,
    wmma::fragment<wmma::accumulator, 16, 16, 8, float> (&acc)[2][4],
    int tr, int wc)
{
#pragma unroll 4
    for (int kc = 0; kc < DH; kc += 8) {
        wmma::fragment<wmma::matrix_a, 16, 16, 8, wmma::precision::tf32, wmma::row_major> a0, a1;
        wmma::load_matrix_sync(a0, As + (tr * 32) * AS_STRIDE + kc, AS_STRIDE);
        wmma::load_matrix_sync(a1, As + (tr * 32 + 16) * AS_STRIDE + kc, AS_STRIDE);
#pragma unroll
        for (int j = 0; j < 4; j++) {
            wmma::fragment<wmma::matrix_b, 16, 16, 8, wmma::precision::tf32, wmma::row_major> b;
            wmma::load_matrix_sync(b, Ws + kc * AS_STRIDE + wc * 64 + j * 16, AS_STRIDE);
            wmma::mma_sync(acc[0][j], a0, b, acc[0][j]);
            wmma::mma_sync(acc[1][j], a1, b, acc[1][j]);
        }
    }
}

__global__ __launch_bounds__(256, 1) void mlp_k(
    const float* __restrict__ A, const float* __restrict__ W1,
    const float* __restrict__ b1, const float* __restrict__ gam,
    const float* __restrict__ bet, const float* __restrict__ W2,
    const float* __restrict__ b2, float* __restrict__ Out)
{
    extern __shared__ float sm[];
    float* As  = sm + AS_OFF;
    float* Ws  = sm + WS_OFF;
    float* bs  = sm + P_OFF;
    float* gs  = bs + 128;
    float* bes = gs + 128;
    float* b2s = bes + 128;
    float* mus = b2s + 128;
    float* invs = mus + 128;

    int tid = threadIdx.x;
    size_t n0 = (size_t)blockIdx.x * 128;

    if (tid < 128) {
        bs[tid]  = __ldg(&b1[tid]);
        gs[tid]  = __ldg(&gam[tid]);
        bes[tid] = __ldg(&bet[tid]);
        b2s[tid] = __ldg(&b2[tid]);
    }

    // load A and W1 into smem, converting to tf32 once
    {
        const float4* ap = reinterpret_cast<const float4*>(A + n0 * DH);
        const float4* wp = reinterpret_cast<const float4*>(W1);
#pragma unroll
        for (int it = 0; it < 16; it++) {
            int i = tid + it * 256;
            int r = i >> 5, c = i & 31;
            float4 v = __ldg(ap + i);
            v.x = wmma::__float_to_tf32(v.x); v.y = wmma::__float_to_tf32(v.y);
            v.z = wmma::__float_to_tf32(v.z); v.w = wmma::__float_to_tf32(v.w);
            reinterpret_cast<float4*>(As + r * AS_STRIDE)[c] = v;
            float4 w = __ldg(wp + i);
            w.x = wmma::__float_to_tf32(w.x); w.y = wmma::__float_to_tf32(w.y);
            w.z = wmma::__float_to_tf32(w.z); w.w = wmma::__float_to_tf32(w.w);
            reinterpret_cast<float4*>(Ws + r * AS_STRIDE)[c] = w;
        }
    }
    __syncthreads();

    int wid = tid >> 5;
    int tr = wid >> 1, wc = wid & 1;

    wmma::fragment<wmma::accumulator, 16, 16, 8, float> acc[2][4];
#pragma unroll
    for (int i = 0; i < 2; i++)
#pragma unroll
        for (int j = 0; j < 4; j++) wmma::fill_fragment(acc[i][j], 0.0f);

    do_gemm(As, Ws, acc, tr, wc);
    __syncthreads();

    // stage GEMM1 result into As; load W2 into Ws
#pragma unroll
    for (int i = 0; i < 2; i++)
#pragma unroll
        for (int j = 0; j < 4; j++)
            wmma::store_matrix_sync(As + (tr * 32 + i * 16) * AS_STRIDE + wc * 64 + j * 16,
                                    acc[i][j], AS_STRIDE, wmma::mem_row_major);
    {
        const float4* wp = reinterpret_cast<const float4*>(W2);
#pragma unroll
        for (int it = 0; it < 16; it++) {
            int i = tid + it * 256;
            int r = i >> 5, c = i & 31;
            float4 w = __ldg(wp + i);
            w.x = wmma::__float_to_tf32(w.x); w.y = wmma::__float_to_tf32(w.y);
            w.z = wmma::__float_to_tf32(w.z); w.w = wmma::__float_to_tf32(w.w);
            reinterpret_cast<float4*>(Ws + r * AS_STRIDE)[c] = w;
        }
    }
    __syncthreads();

    // LN stats: 2 threads per row
    int row = tid >> 1, half = tid & 1;
    {
        const float* rp = As + row * AS_STRIDE + half * 64;
        const float* bp = bs + half * 64;
        float s = 0.f, ss = 0.f;
#pragma unroll
        for (int c = 0; c < 64; c++) {
            float xv = rp[c] + bp[c];
            s += xv; ss += xv * xv;
        }
        s  += __shfl_xor_sync(0xffffffffu, s, 1);
        ss += __shfl_xor_sync(0xffffffffu, ss, 1);
        if (half == 0) {
            float mu = s * (1.0f / 128.0f);
            float var = ss * (1.0f / 128.0f) - mu * mu;
            mus[row] = mu;
            invs[row] = rsqrtf(var + LN_EPSF);
        }
    }
    __syncthreads();

    // normalize + relu in place (tf32 convert for GEMM2)
    {
        float mu = mus[row], inv = invs[row];
        float* wrp = As + row * AS_STRIDE + half * 64;
        const float* bp = bs + half * 64;
        const float* gp = gs + half * 64;
        const float* ep = bes + half * 64;
#pragma unroll
        for (int c = 0; c < 64; c++) {
            float xv = wrp[c] + bp[c];
            float y = (xv - mu) * inv * gp[c] + ep[c];
            wrp[c] = wmma::__float_to_tf32(fmaxf(y, 0.f));
        }
    }
    __syncthreads();

#pragma unroll
    for (int i = 0; i < 2; i++)
#pragma unroll
        for (int j = 0; j < 4; j++) wmma::fill_fragment(acc[i][j], 0.0f);

    do_gemm(As, Ws, acc, tr, wc);
    __syncthreads();

#pragma unroll
    for (int i = 0; i < 2; i++)
#pragma unroll
        for (int j = 0; j < 4; j++)
            wmma::store_matrix_sync(As + (tr * 32 + i * 16) * AS_STRIDE + wc * 64 + j * 16,
                                    acc[i][j], AS_STRIDE, wmma::mem_row_major);
    __syncthreads();

    {
        float4* op = reinterpret_cast<float4*>(Out + n0 * DH);
        const float4* b4 = reinterpret_cast<const float4*>(b2s);
#pragma unroll
        for (int it = 0; it < 16; it++) {
            int i = tid + it * 256;
            int r = i >> 5, c = i & 31;
            float4 v = reinterpret_cast<float4*>(As + r * AS_STRIDE)[c];
            float4 bv = b4[c];
            v.x += bv.x; v.y += bv.y; v.z += bv.z; v.w += bv.w;
            op[i] = v;
        }
    }
}

// ---------------- per-graph node sum ------------------------------------------
__global__ void sum_k(float* __restrict__ out, int off) {
    int g = blockIdx.x, d = threadIdx.x;
    const float* base = g_h + (size_t)g * NNODE * DH + d;
    float s = 0.f;
#pragma unroll 8
    for (int j = 0; j < NNODE; j++) s += base[(size_t)j * DH];
    out[g * 256 + off + d] = s;
}

// ---------------- launch ------------------------------------------------------
extern "C" void kernel_launch(void* const* d_in, const int* in_sizes, int n_in,
                              void* d_out, int out_size)
{
    const int*   x     = (const int*)d_in[0];
    const int*   ei    = (const int*)d_in[1];
    const int*   los   = (const int*)d_in[2];
    const float* emb   = (const float*)d_in[3];
    const float* lt    = (const float*)d_in[4];
    const float* g1w1  = (const float*)d_in[5];
    const float* g1b1  = (const float*)d_in[6];
    const float* g1g   = (const float*)d_in[7];
    const float* g1be  = (const float*)d_in[8];
    const float* g1w2  = (const float*)d_in[9];
    const float* g1b2  = (const float*)d_in[10];
    const float* g1eps = (const float*)d_in[11];
    const float* g2w1  = (const float*)d_in[12];
    const float* g2b1  = (const float*)d_in[13];
    const float* g2g   = (const float*)d_in[14];
    const float* g2be  = (const float*)d_in[15];
    const float* g2w2  = (const float*)d_in[16];
    const float* g2b2  = (const float*)d_in[17];
    const float* g2eps = (const float*)d_in[18];
    const float* g2ew  = (const float*)d_in[19];
    const float* g2eb  = (const float*)d_in[20];
    float* out = (float*)d_out;

    const int* src = ei;
    const int* dst = ei + EINT;

    void *ph, *pz, *pc;
    cudaGetSymbolAddress(&ph, g_h);
    cudaGetSymbolAddress(&pz, g_z);
    cudaGetSymbolAddress(&pc, g_cnt);
    float* hB = (float*)ph;
    float* zB = (float*)pz;

    static int smem_set = 0;
    if (!smem_set) {
        cudaFuncSetAttribute(mlp_k, cudaFuncAttributeMaxDynamicSharedMemorySize,
                             MLP_SMEM_BYTES);
        smem_set = 1;
    }

    embed_k<<<(NTOT * 32) / 256, 256>>>(x, emb);

    // CSR build (edge list fixed for all 4 rounds)
    cudaMemsetAsync(pc, 0, NTOT * sizeof(int));
    hist_k<<<EINT / 256, 256>>>(dst);
    scanA_k<<<NTOT / 256, 256>>>();
    scanB_k<<<1, 512>>>();
    scanC_k<<<NTOT / 256, 256>>>();
    fill_k<<<EINT / 256, 256>>>(src, dst);

    // ---- GIN layer group 1 ----
    for (int i = 0; i < 2; i++) {
        agg1_k<<<(NTOT * 32) / 256, 256>>>(g1eps + i);
        mlp_k<<<NTOT / 128, 256, MLP_SMEM_BYTES>>>(
            zB, g1w1 + (size_t)i * DH * DH, g1b1 + i * DH, g1g + i * DH,
            g1be + i * DH, g1w2 + (size_t)i * DH * DH, g1b2 + i * DH, hB);
    }
    sum_k<<<2 * NB, DH>>>(out, 0);

    // ---- GINE layer group 2 ----
    for (int i = 0; i < 2; i++) {
        table_k<<<38, DH>>>(lt, g2ew + (size_t)i * 8 * DH, g2eb + i * DH);
        agg2_k<<<(NTOT * 32) / 256, 256>>>(g2eps + i, los);
        mlp_k<<<NTOT / 128, 256, MLP_SMEM_BYTES>>>(
            zB, g2w1 + (size_t)i * DH * DH, g2b1 + i * DH, g2g + i * DH,
            g2be + i * DH, g2w2 + (size_t)i * DH * DH, g2b2 + i * DH, hB);
    }
    sum_k<<<2 * NB, DH>>>(out, 128);
}

// round 3
// speedup vs baseline: 1.4301x; 1.0335x over previous
#include <cuda_runtime.h>
#include <mma.h>
#include <cstdint>

using namespace nvcuda;

#define NB      256
#define NCOLS   512
#define NNODE   256
#define VOCAB   100
#define DH      128
#define NTOT    (2*NB*NNODE)      /* 131072 nodes */
#define EINT    (NTOT*8)          /* 1048576 edges */
#define MERGED  (NB*NNODE)        /* 65536 */
#define LN_EPSF 1e-5f

// ---------------- scratch (device globals; no allocation allowed) -----------
__device__ float g_h[(size_t)NTOT * DH];   // node features
__device__ float g_z[(size_t)NTOT * DH];   // (1+eps)*h + agg (tf32-rounded)
__device__ float g_tab[38 * DH];           // los_table @ ew + eb (per layer)
__device__ float g_w[8][DH * DH];          // tf32-converted weights
__device__ int   g_cnt[NTOT];              // in-degree
__device__ int   g_off[NTOT];              // CSR offsets (exclusive)
__device__ int   g_cur[NTOT];              // fill cursors
__device__ int   g_eid[EINT];              // src ids grouped by dst
__device__ int   g_part[512];              // scan partials

// ---------------- weight pre-convert to tf32 ---------------------------------
__global__ void convw_k(const float* p0, const float* p1, const float* p2,
                        const float* p3, const float* p4, const float* p5,
                        const float* p6, const float* p7) {
    int m = blockIdx.y;
    const float* p = (m == 0) ? p0 : (m == 1) ? p1 : (m == 2) ? p2 : (m == 3) ? p3
                   : (m == 4) ? p4 : (m == 5) ? p5 : (m == 6) ? p6 : p7;
    int i = blockIdx.x * 256 + threadIdx.x;
    g_w[m][i] = wmma::__float_to_tf32(__ldg(&p[i]));
}

// ---------------- embedding gather ------------------------------------------
__global__ void embed_k(const int* __restrict__ x, const float* __restrict__ emb) {
    int tid = blockIdx.x * blockDim.x + threadIdx.x;
    int n = tid >> 5, l = tid & 31;
    if (n >= NTOT) return;
    int c = n & (NCOLS - 1);
    int b = n >> 9;
    int v = __ldg(&x[b * NCOLS + c]);
    float4 val = __ldg(reinterpret_cast<const float4*>(emb + ((size_t)c * VOCAB + v) * DH) + l);
    reinterpret_cast<float4*>(g_h + (size_t)n * DH)[l] = val;
}

// ---------------- CSR build ---------------------------------------------------
__global__ void hist_k(const int* __restrict__ dst) {
    int e = blockIdx.x * 256 + threadIdx.x;
    if (e < EINT) atomicAdd(&g_cnt[__ldg(&dst[e])], 1);
}

__global__ void scanA_k() {
    __shared__ int s[256];
    int t = threadIdx.x;
    int i = blockIdx.x * 256 + t;
    int c = g_cnt[i];
    s[t] = c;
    __syncthreads();
#pragma unroll
    for (int o = 1; o < 256; o <<= 1) {
        int v = (t >= o) ? s[t - o] : 0;
        __syncthreads();
        s[t] += v;
        __syncthreads();
    }
    g_off[i] = s[t];
    if (t == 255) g_part[blockIdx.x] = s[255];
}

__global__ void scanB_k() {
    __shared__ int s[512];
    int t = threadIdx.x;
    int c = g_part[t];
    s[t] = c;
    __syncthreads();
#pragma unroll
    for (int o = 1; o < 512; o <<= 1) {
        int v = (t >= o) ? s[t - o] : 0;
        __syncthreads();
        s[t] += v;
        __syncthreads();
    }
    g_part[t] = s[t] - c;
}

__global__ void scanC_k() {
    int i = blockIdx.x * 256 + threadIdx.x;
    int off = g_off[i] - g_cnt[i] + g_part[blockIdx.x];
    g_off[i] = off;
    g_cur[i] = off;
}

__global__ void fill_k(const int* __restrict__ src, const int* __restrict__ dst) {
    int e = blockIdx.x * 256 + threadIdx.x;
    if (e >= EINT) return;
    int d = __ldg(&dst[e]);
    int p = atomicAdd(&g_cur[d], 1);
    g_eid[p] = __ldg(&src[e]);
}

// ---------------- GIN aggregation (writes tf32-rounded z) --------------------
__global__ void agg1_k(const float* __restrict__ epsp) {
    int tid = blockIdx.x * 256 + threadIdx.x;
    int n = tid >> 5, l = tid & 31;
    float s = 1.0f + __ldg(epsp);
    const float4* h4 = reinterpret_cast<const float4*>(g_h);
    float4 a = h4[(size_t)n * 32 + l];
    float4 acc = make_float4(a.x * s, a.y * s, a.z * s, a.w * s);
    int off = g_off[n], deg = g_cnt[n];
    int k = 0;
    for (; k + 4 <= deg; k += 4) {
        int e0 = g_eid[off + k], e1 = g_eid[off + k + 1];
        int e2 = g_eid[off + k + 2], e3 = g_eid[off + k + 3];
        float4 v0 = __ldg(&h4[(size_t)e0 * 32 + l]);
        float4 v1 = __ldg(&h4[(size_t)e1 * 32 + l]);
        float4 v2 = __ldg(&h4[(size_t)e2 * 32 + l]);
        float4 v3 = __ldg(&h4[(size_t)e3 * 32 + l]);
        acc.x += v0.x + v1.x + v2.x + v3.x;
        acc.y += v0.y + v1.y + v2.y + v3.y;
        acc.z += v0.z + v1.z + v2.z + v3.z;
        acc.w += v0.w + v1.w + v2.w + v3.w;
    }
    for (; k < deg; k++) {
        int e0 = g_eid[off + k];
        float4 v = __ldg(&h4[(size_t)e0 * 32 + l]);
        acc.x += v.x; acc.y += v.y; acc.z += v.z; acc.w += v.w;
    }
    acc.x = wmma::__float_to_tf32(acc.x);
    acc.y = wmma::__float_to_tf32(acc.y);
    acc.z = wmma::__float_to_tf32(acc.z);
    acc.w = wmma::__float_to_tf32(acc.w);
    reinterpret_cast<float4*>(g_z)[(size_t)n * 32 + l] = acc;
}

// ---------------- GINE aggregation (writes tf32-rounded z) -------------------
__global__ void agg2_k(const float* __restrict__ epsp, const int* __restrict__ los) {
    int tid = blockIdx.x * 256 + threadIdx.x;
    int n = tid >> 5, l = tid & 31;
    float s = 1.0f + __ldg(epsp);
    const float4* h4 = reinterpret_cast<const float4*>(g_h);
    const float4* t4 = reinterpret_cast<const float4*>(g_tab);
    float4 c0 = t4[l];
    float4 a = h4[(size_t)n * 32 + l];
    float4 acc = make_float4(a.x * s, a.y * s, a.z * s, a.w * s);
    int off = g_off[n], deg = g_cnt[n];
    int k = 0;
    for (; k + 4 <= deg; k += 4) {
        int e0 = g_eid[off + k], e1 = g_eid[off + k + 1];
        int e2 = g_eid[off + k + 2], e3 = g_eid[off + k + 3];
        float4 v0 = __ldg(&h4[(size_t)e0 * 32 + l]);
        float4 v1 = __ldg(&h4[(size_t)e1 * 32 + l]);
        float4 v2 = __ldg(&h4[(size_t)e2 * 32 + l]);
        float4 v3 = __ldg(&h4[(size_t)e3 * 32 + l]);
        acc.x += fmaxf(v0.x + c0.x, 0.f) + fmaxf(v1.x + c0.x, 0.f) + fmaxf(v2.x + c0.x, 0.f) + fmaxf(v3.x + c0.x, 0.f);
        acc.y += fmaxf(v0.y + c0.y, 0.f) + fmaxf(v1.y + c0.y, 0.f) + fmaxf(v2.y + c0.y, 0.f) + fmaxf(v3.y + c0.y, 0.f);
        acc.z += fmaxf(v0.z + c0.z, 0.f) + fmaxf(v1.z + c0.z, 0.f) + fmaxf(v2.z + c0.z, 0.f) + fmaxf(v3.z + c0.z, 0.f);
        acc.w += fmaxf(v0.w + c0.w, 0.f) + fmaxf(v1.w + c0.w, 0.f) + fmaxf(v2.w + c0.w, 0.f) + fmaxf(v3.w + c0.w, 0.f);
    }
    for (; k < deg; k++) {
        int e0 = g_eid[off + k];
        float4 v = __ldg(&h4[(size_t)e0 * 32 + l]);
        acc.x += fmaxf(v.x + c0.x, 0.f);
        acc.y += fmaxf(v.y + c0.y, 0.f);
        acc.z += fmaxf(v.z + c0.z, 0.f);
        acc.w += fmaxf(v.w + c0.w, 0.f);
    }
    if (n >= MERGED) {
        int m = n - MERGED;
        int lo = __ldg(&los[m >> 8]);
        float4 t = t4[lo * 32 + l];
        float4 v = h4[(size_t)m * 32 + l];
        acc.x += fmaxf(v.x + t.x, 0.f);
        acc.y += fmaxf(v.y + t.y, 0.f);
        acc.z += fmaxf(v.z + t.z, 0.f);
        acc.w += fmaxf(v.w + t.w, 0.f);
    }
    acc.x = wmma::__float_to_tf32(acc.x);
    acc.y = wmma::__float_to_tf32(acc.y);
    acc.z = wmma::__float_to_tf32(acc.z);
    acc.w = wmma::__float_to_tf32(acc.w);
    reinterpret_cast<float4*>(g_z)[(size_t)n * 32 + l] = acc;
}

// ---------------- tab[r][:] = los_table[r] @ ew + eb --------------------------
__global__ void table_k(const float* __restrict__ lt, const float* __restrict__ ew,
                        const float* __restrict__ eb) {
    int r = blockIdx.x, d = threadIdx.x;
    float acc = __ldg(&eb[d]);
#pragma unroll
    for (int j = 0; j < 8; j++)
        acc += __ldg(&lt[r * 8 + j]) * __ldg(&ew[j * DH + d]);
    g_tab[r * DH + d] = acc;
}

// ---------------- fused MLP: Out = relu(LN(A@W1+b1))@W2 + b2 ------------------
// A-fragments and B-fragments load DIRECTLY from global (tf32 pre-rounded).
// smem holds only the intermediate tile + params -> 2 CTAs/SM.
#define IS_STRIDE 132
#define MLP_SMEM_BYTES ((128*IS_STRIDE + 6*128) * 4)

__device__ __forceinline__ void do_gemm(
    const float* __restrict__ A, int lda, const float* __restrict__ B,
    wmma::fragment<wmma::accumulator, 16, 16, 8, float> (&acc)[2][4],
    int tr, int wc)
{
#pragma unroll 4
    for (int kc = 0; kc < DH; kc += 8) {
        wmma::fragment<wmma::matrix_a, 16, 16, 8, wmma::precision::tf32, wmma::row_major> a0, a1;
        wmma::load_matrix_sync(a0, A + (size_t)(tr * 32) * lda + kc, lda);
        wmma::load_matrix_sync(a1, A + (size_t)(tr * 32 + 16) * lda + kc, lda);
#pragma unroll
        for (int j = 0; j < 4; j++) {
            wmma::fragment<wmma::matrix_b, 16, 16, 8, wmma::precision::tf32, wmma::row_major> b;
            wmma::load_matrix_sync(b, B + kc * DH + wc * 64 + j * 16, DH);
            wmma::mma_sync(acc[0][j], a0, b, acc[0][j]);
            wmma::mma_sync(acc[1][j], a1, b, acc[1][j]);
        }
    }
}

__global__ __launch_bounds__(256, 2) void mlp_k(
    const float* __restrict__ A, const float* __restrict__ W1,
    const float* __restrict__ b1, const float* __restrict__ gam,
    const float* __restrict__ bet, const float* __restrict__ W2,
    const float* __restrict__ b2, float* __restrict__ Out)
{
    extern __shared__ float sm[];
    float* inter = sm;                     // 128 x 132
    float* bs   = sm + 128 * IS_STRIDE;
    float* gs   = bs + 128;
    float* bes  = gs + 128;
    float* b2s  = bes + 128;
    float* mus  = b2s + 128;
    float* invs = mus + 128;

    int tid = threadIdx.x;
    size_t n0 = (size_t)blockIdx.x * 128;

    if (tid < 128) {
        bs[tid]  = __ldg(&b1[tid]);
        gs[tid]  = __ldg(&gam[tid]);
        bes[tid] = __ldg(&bet[tid]);
        b2s[tid] = __ldg(&b2[tid]);
    }

    int wid = tid >> 5;
    int tr = wid >> 1, wc = wid & 1;

    wmma::fragment<wmma::accumulator, 16, 16, 8, float> acc[2][4];
#pragma unroll
    for (int i = 0; i < 2; i++)
#pragma unroll
        for (int j = 0; j < 4; j++) wmma::fill_fragment(acc[i][j], 0.0f);

    // GEMM1: A from global z (tf32), B from global W1 (tf32)
    do_gemm(A + n0 * DH, DH, W1, acc, tr, wc);

    // stage GEMM1 result into smem
#pragma unroll
    for (int i = 0; i < 2; i++)
#pragma unroll
        for (int j = 0; j < 4; j++)
            wmma::store_matrix_sync(inter + (tr * 32 + i * 16) * IS_STRIDE + wc * 64 + j * 16,
                                    acc[i][j], IS_STRIDE, wmma::mem_row_major);
    __syncthreads();

    // LN stats: 2 threads per row
    int row = tid >> 1, half = tid & 1;
    {
        const float* rp = inter + row * IS_STRIDE + half * 64;
        const float* bp = bs + half * 64;
        float s = 0.f, ss = 0.f;
#pragma unroll
        for (int c = 0; c < 64; c++) {
            float xv = rp[c] + bp[c];
            s += xv; ss += xv * xv;
        }
        s  += __shfl_xor_sync(0xffffffffu, s, 1);
        ss += __shfl_xor_sync(0xffffffffu, ss, 1);
        if (half == 0) {
            float mu = s * (1.0f / 128.0f);
            float var = ss * (1.0f / 128.0f) - mu * mu;
            mus[row] = mu;
            invs[row] = rsqrtf(var + LN_EPSF);
        }
    }
    __syncthreads();

    // normalize + relu in place (tf32 rounding for GEMM2)
    {
        float mu = mus[row], inv = invs[row];
        float* wrp = inter + row * IS_STRIDE + half * 64;
        const float* bp = bs + half * 64;
        const float* gp = gs + half * 64;
        const float* ep = bes + half * 64;
#pragma unroll
        for (int c = 0; c < 64; c++) {
            float xv = wrp[c] + bp[c];
            float y = (xv - mu) * inv * gp[c] + ep[c];
            wrp[c] = wmma::__float_to_tf32(fmaxf(y, 0.f));
        }
    }
    __syncthreads();

#pragma unroll
    for (int i = 0; i < 2; i++)
#pragma unroll
        for (int j = 0; j < 4; j++) wmma::fill_fragment(acc[i][j], 0.0f);

    // GEMM2: A from smem intermediate, B from global W2 (tf32)
    do_gemm(inter, IS_STRIDE, W2, acc, tr, wc);
    __syncthreads();

#pragma unroll
    for (int i = 0; i < 2; i++)
#pragma unroll
        for (int j = 0; j < 4; j++)
            wmma::store_matrix_sync(inter + (tr * 32 + i * 16) * IS_STRIDE + wc * 64 + j * 16,
                                    acc[i][j], IS_STRIDE, wmma::mem_row_major);
    __syncthreads();

    {
        float4* op = reinterpret_cast<float4*>(Out + n0 * DH);
        const float4* b4 = reinterpret_cast<const float4*>(b2s);
#pragma unroll
        for (int it = 0; it < 16; it++) {
            int i = tid + it * 256;
            int r = i >> 5, c = i & 31;
            float4 v = reinterpret_cast<float4*>(inter + r * IS_STRIDE)[c];
            float4 bv = b4[c];
            v.x += bv.x; v.y += bv.y; v.z += bv.z; v.w += bv.w;
            op[i] = v;
        }
    }
}

// ---------------- per-graph node sum ------------------------------------------
__global__ void sum_k(float* __restrict__ out, int off) {
    int g = blockIdx.x, d = threadIdx.x;
    const float* base = g_h + (size_t)g * NNODE * DH + d;
    float s = 0.f;
#pragma unroll 8
    for (int j = 0; j < NNODE; j++) s += base[(size_t)j * DH];
    out[g * 256 + off + d] = s;
}

// ---------------- launch ------------------------------------------------------
extern "C" void kernel_launch(void* const* d_in, const int* in_sizes, int n_in,
                              void* d_out, int out_size)
{
    const int*   x     = (const int*)d_in[0];
    const int*   ei    = (const int*)d_in[1];
    const int*   los   = (const int*)d_in[2];
    const float* emb   = (const float*)d_in[3];
    const float* lt    = (const float*)d_in[4];
    const float* g1w1  = (const float*)d_in[5];
    const float* g1b1  = (const float*)d_in[6];
    const float* g1g   = (const float*)d_in[7];
    const float* g1be  = (const float*)d_in[8];
    const float* g1w2  = (const float*)d_in[9];
    const float* g1b2  = (const float*)d_in[10];
    const float* g1eps = (const float*)d_in[11];
    const float* g2w1  = (const float*)d_in[12];
    const float* g2b1  = (const float*)d_in[13];
    const float* g2g   = (const float*)d_in[14];
    const float* g2be  = (const float*)d_in[15];
    const float* g2w2  = (const float*)d_in[16];
    const float* g2b2  = (const float*)d_in[17];
    const float* g2eps = (const float*)d_in[18];
    const float* g2ew  = (const float*)d_in[19];
    const float* g2eb  = (const float*)d_in[20];
    float* out = (float*)d_out;

    const int* src = ei;
    const int* dst = ei + EINT;

    void *ph, *pz, *pc, *pw;
    cudaGetSymbolAddress(&ph, g_h);
    cudaGetSymbolAddress(&pz, g_z);
    cudaGetSymbolAddress(&pc, g_cnt);
    cudaGetSymbolAddress(&pw, g_w);
    float* hB = (float*)ph;
    float* zB = (float*)pz;
    float* wB = (float*)pw;

    static int smem_set = 0;
    if (!smem_set) {
        cudaFuncSetAttribute(mlp_k, cudaFuncAttributeMaxDynamicSharedMemorySize,
                             MLP_SMEM_BYTES);
        smem_set = 1;
    }

    // weight pre-convert: order [g1w1L0, g1w2L0, g1w1L1, g1w2L1, g2w1L0, g2w2L0, g2w1L1, g2w2L1]
    convw_k<<<dim3(64, 8), 256>>>(
        g1w1, g1w2, g1w1 + DH * DH, g1w2 + DH * DH,
        g2w1, g2w2, g2w1 + DH * DH, g2w2 + DH * DH);

    embed_k<<<(NTOT * 32) / 256, 256>>>(x, emb);

    // CSR build
    cudaMemsetAsync(pc, 0, NTOT * sizeof(int));
    hist_k<<<EINT / 256, 256>>>(dst);
    scanA_k<<<NTOT / 256, 256>>>();
    scanB_k<<<1, 512>>>();
    scanC_k<<<NTOT / 256, 256>>>();
    fill_k<<<EINT / 256, 256>>>(src, dst);

    // ---- GIN layer group 1 ----
    for (int i = 0; i < 2; i++) {
        agg1_k<<<(NTOT * 32) / 256, 256>>>(g1eps + i);
        mlp_k<<<NTOT / 128, 256, MLP_SMEM_BYTES>>>(
            zB, wB + (size_t)(2 * i) * DH * DH, g1b1 + i * DH, g1g + i * DH,
            g1be + i * DH, wB + (size_t)(2 * i + 1) * DH * DH, g1b2 + i * DH, hB);
    }
    sum_k<<<2 * NB, DH>>>(out, 0);

    // ---- GINE layer group 2 ----
    for (int i = 0; i < 2; i++) {
        table_k<<<38, DH>>>(lt, g2ew + (size_t)i * 8 * DH, g2eb + i * DH);
        agg2_k<<<(NTOT * 32) / 256, 256>>>(g2eps + i, los);
        mlp_k<<<NTOT / 128, 256, MLP_SMEM_BYTES>>>(
            zB, wB + (size_t)(4 + 2 * i) * DH * DH, g2b1 + i * DH, g2g + i * DH,
            g2be + i * DH, wB + (size_t)(5 + 2 * i) * DH * DH, g2b2 + i * DH, hB);
    }
    sum_k<<<2 * NB, DH>>>(out, 128);
}

// round 4
// speedup vs baseline: 1.4436x; 1.0094x over previous
#include <cuda_runtime.h>
#include <mma.h>
#include <cstdint>

using namespace nvcuda;

#define NB      256
#define NCOLS   512
#define NNODE   256
#define VOCAB   100
#define DH      128
#define NTOT    (2*NB*NNODE)      /* 131072 nodes */
#define EINT    (NTOT*8)          /* 1048576 edges */
#define MERGED  (NB*NNODE)        /* 65536 */
#define LN_EPSF 1e-5f

// ---------------- scratch (device globals; no allocation allowed) -----------
__device__ float g_h[(size_t)NTOT * DH];   // node features
__device__ float g_z[(size_t)NTOT * DH];   // (1+eps)*h + agg (tf32-rounded)
__device__ float g_tab[38 * DH];           // los_table @ ew + eb (per layer)
__device__ float g_w[8][DH * DH];          // tf32-converted weights
__device__ int   g_cnt[NTOT];              // in-degree
__device__ int   g_off[NTOT];              // CSR offsets (exclusive)
__device__ int   g_cur[NTOT];              // fill cursors
__device__ int   g_eid[EINT];              // src ids grouped by dst
__device__ int   g_part[512];              // scan partials

// ---------------- weight pre-convert to tf32 ---------------------------------
__global__ void convw_k(const float* p0, const float* p1, const float* p2,
                        const float* p3, const float* p4, const float* p5,
                        const float* p6, const float* p7) {
    int m = blockIdx.y;
    const float* p = (m == 0) ? p0 : (m == 1) ? p1 : (m == 2) ? p2 : (m == 3) ? p3
                   : (m == 4) ? p4 : (m == 5) ? p5 : (m == 6) ? p6 : p7;
    int i = blockIdx.x * 256 + threadIdx.x;
    g_w[m][i] = wmma::__float_to_tf32(__ldg(&p[i]));
}

// ---------------- embedding gather ------------------------------------------
__global__ void embed_k(const int* __restrict__ x, const float* __restrict__ emb) {
    int tid = blockIdx.x * blockDim.x + threadIdx.x;
    int n = tid >> 5, l = tid & 31;
    if (n >= NTOT) return;
    int c = n & (NCOLS - 1);
    int b = n >> 9;
    int v = __ldg(&x[b * NCOLS + c]);
    float4 val = __ldg(reinterpret_cast<const float4*>(emb + ((size_t)c * VOCAB + v) * DH) + l);
    reinterpret_cast<float4*>(g_h + (size_t)n * DH)[l] = val;
}

// ---------------- CSR build ---------------------------------------------------
__global__ void hist_k(const int* __restrict__ dst) {
    int e = blockIdx.x * 256 + threadIdx.x;
    if (e < EINT) atomicAdd(&g_cnt[__ldg(&dst[e])], 1);
}

__global__ void scanA_k() {
    __shared__ int s[256];
    int t = threadIdx.x;
    int i = blockIdx.x * 256 + t;
    int c = g_cnt[i];
    s[t] = c;
    __syncthreads();
#pragma unroll
    for (int o = 1; o < 256; o <<= 1) {
        int v = (t >= o) ? s[t - o] : 0;
        __syncthreads();
        s[t] += v;
        __syncthreads();
    }
    g_off[i] = s[t];
    if (t == 255) g_part[blockIdx.x] = s[255];
}

__global__ void scanB_k() {
    __shared__ int s[512];
    int t = threadIdx.x;
    int c = g_part[t];
    s[t] = c;
    __syncthreads();
#pragma unroll
    for (int o = 1; o < 512; o <<= 1) {
        int v = (t >= o) ? s[t - o] : 0;
        __syncthreads();
        s[t] += v;
        __syncthreads();
    }
    g_part[t] = s[t] - c;
}

__global__ void scanC_k() {
    int i = blockIdx.x * 256 + threadIdx.x;
    int off = g_off[i] - g_cnt[i] + g_part[blockIdx.x];
    g_off[i] = off;
    g_cur[i] = off;
}

__global__ void fill_k(const int* __restrict__ src, const int* __restrict__ dst) {
    int e = blockIdx.x * 256 + threadIdx.x;
    if (e >= EINT) return;
    int d = __ldg(&dst[e]);
    int p = atomicAdd(&g_cur[d], 1);
    g_eid[p] = __ldg(&src[e]);
}

// ---------------- GIN aggregation (writes tf32-rounded z) --------------------
__global__ void agg1_k(const float* __restrict__ epsp) {
    int tid = blockIdx.x * 256 + threadIdx.x;
    int n = tid >> 5, l = tid & 31;
    float s = 1.0f + __ldg(epsp);
    const float4* h4 = reinterpret_cast<const float4*>(g_h);
    float4 a = h4[(size_t)n * 32 + l];
    float4 acc = make_float4(a.x * s, a.y * s, a.z * s, a.w * s);
    int off = g_off[n], deg = g_cnt[n];
    int k = 0;
    for (; k + 4 <= deg; k += 4) {
        int e0 = g_eid[off + k], e1 = g_eid[off + k + 1];
        int e2 = g_eid[off + k + 2], e3 = g_eid[off + k + 3];
        float4 v0 = __ldg(&h4[(size_t)e0 * 32 + l]);
        float4 v1 = __ldg(&h4[(size_t)e1 * 32 + l]);
        float4 v2 = __ldg(&h4[(size_t)e2 * 32 + l]);
        float4 v3 = __ldg(&h4[(size_t)e3 * 32 + l]);
        acc.x += v0.x + v1.x + v2.x + v3.x;
        acc.y += v0.y + v1.y + v2.y + v3.y;
        acc.z += v0.z + v1.z + v2.z + v3.z;
        acc.w += v0.w + v1.w + v2.w + v3.w;
    }
    for (; k < deg; k++) {
        int e0 = g_eid[off + k];
        float4 v = __ldg(&h4[(size_t)e0 * 32 + l]);
        acc.x += v.x; acc.y += v.y; acc.z += v.z; acc.w += v.w;
    }
    acc.x = wmma::__float_to_tf32(acc.x);
    acc.y = wmma::__float_to_tf32(acc.y);
    acc.z = wmma::__float_to_tf32(acc.z);
    acc.w = wmma::__float_to_tf32(acc.w);
    reinterpret_cast<float4*>(g_z)[(size_t)n * 32 + l] = acc;
}

// ---------------- GINE aggregation (writes tf32-rounded z) -------------------
__global__ void agg2_k(const float* __restrict__ epsp, const int* __restrict__ los) {
    int tid = blockIdx.x * 256 + threadIdx.x;
    int n = tid >> 5, l = tid & 31;
    float s = 1.0f + __ldg(epsp);
    const float4* h4 = reinterpret_cast<const float4*>(g_h);
    const float4* t4 = reinterpret_cast<const float4*>(g_tab);
    float4 c0 = t4[l];
    float4 a = h4[(size_t)n * 32 + l];
    float4 acc = make_float4(a.x * s, a.y * s, a.z * s, a.w * s);
    int off = g_off[n], deg = g_cnt[n];
    int k = 0;
    for (; k + 4 <= deg; k += 4) {
        int e0 = g_eid[off + k], e1 = g_eid[off + k + 1];
        int e2 = g_eid[off + k + 2], e3 = g_eid[off + k + 3];
        float4 v0 = __ldg(&h4[(size_t)e0 * 32 + l]);
        float4 v1 = __ldg(&h4[(size_t)e1 * 32 + l]);
        float4 v2 = __ldg(&h4[(size_t)e2 * 32 + l]);
        float4 v3 = __ldg(&h4[(size_t)e3 * 32 + l]);
        acc.x += fmaxf(v0.x + c0.x, 0.f) + fmaxf(v1.x + c0.x, 0.f) + fmaxf(v2.x + c0.x, 0.f) + fmaxf(v3.x + c0.x, 0.f);
        acc.y += fmaxf(v0.y + c0.y, 0.f) + fmaxf(v1.y + c0.y, 0.f) + fmaxf(v2.y + c0.y, 0.f) + fmaxf(v3.y + c0.y, 0.f);
        acc.z += fmaxf(v0.z + c0.z, 0.f) + fmaxf(v1.z + c0.z, 0.f) + fmaxf(v2.z + c0.z, 0.f) + fmaxf(v3.z + c0.z, 0.f);
        acc.w += fmaxf(v0.w + c0.w, 0.f) + fmaxf(v1.w + c0.w, 0.f) + fmaxf(v2.w + c0.w, 0.f) + fmaxf(v3.w + c0.w, 0.f);
    }
    for (; k < deg; k++) {
        int e0 = g_eid[off + k];
        float4 v = __ldg(&h4[(size_t)e0 * 32 + l]);
        acc.x += fmaxf(v.x + c0.x, 0.f);
        acc.y += fmaxf(v.y + c0.y, 0.f);
        acc.z += fmaxf(v.z + c0.z, 0.f);
        acc.w += fmaxf(v.w + c0.w, 0.f);
    }
    if (n >= MERGED) {
        int m = n - MERGED;
        int lo = __ldg(&los[m >> 8]);
        float4 t = t4[lo * 32 + l];
        float4 v = h4[(size_t)m * 32 + l];
        acc.x += fmaxf(v.x + t.x, 0.f);
        acc.y += fmaxf(v.y + t.y, 0.f);
        acc.z += fmaxf(v.z + t.z, 0.f);
        acc.w += fmaxf(v.w + t.w, 0.f);
    }
    acc.x = wmma::__float_to_tf32(acc.x);
    acc.y = wmma::__float_to_tf32(acc.y);
    acc.z = wmma::__float_to_tf32(acc.z);
    acc.w = wmma::__float_to_tf32(acc.w);
    reinterpret_cast<float4*>(g_z)[(size_t)n * 32 + l] = acc;
}

// ---------------- tab[r][:] = los_table[r] @ ew + eb --------------------------
__global__ void table_k(const float* __restrict__ lt, const float* __restrict__ ew,
                        const float* __restrict__ eb) {
    int r = blockIdx.x, d = threadIdx.x;
    float acc = __ldg(&eb[d]);
#pragma unroll
    for (int j = 0; j < 8; j++)
        acc += __ldg(&lt[r * 8 + j]) * __ldg(&ew[j * DH + d]);
    g_tab[r * DH + d] = acc;
}

// ---------------- fused MLP: Out = relu(LN(A@W1+b1))@W2 + b2 ------------------
// A-fragments and B-fragments load DIRECTLY from global (tf32 pre-rounded).
// smem holds only the intermediate tile + params -> 2 CTAs/SM.
#define IS_STRIDE 132
#define MLP_SMEM_BYTES ((128*IS_STRIDE + 6*128) * 4)

__device__ __forceinline__ void do_gemm(
    const float* __restrict__ A, int lda, const float* __restrict__ B,
    wmma::fragment<wmma::accumulator, 16, 16, 8, float> (&acc)[2][4],
    int tr, int wc)
{
#pragma unroll 4
    for (int kc = 0; kc < DH; kc += 8) {
        wmma::fragment<wmma::matrix_a, 16, 16, 8, wmma::precision::tf32, wmma::row_major> a0, a1;
        wmma::load_matrix_sync(a0, A + (size_t)(tr * 32) * lda + kc, lda);
        wmma::load_matrix_sync(a1, A + (size_t)(tr * 32 + 16) * lda + kc, lda);
#pragma unroll
        for (int j = 0; j < 4; j++) {
            wmma::fragment<wmma::matrix_b, 16, 16, 8, wmma::precision::tf32, wmma::row_major> b;
            wmma::load_matrix_sync(b, B + kc * DH + wc * 64 + j * 16, DH);
            wmma::mma_sync(acc[0][j], a0, b, acc[0][j]);
            wmma::mma_sync(acc[1][j], a1, b, acc[1][j]);
        }
    }
}

__global__ __launch_bounds__(256, 2) void mlp_k(
    const float* __restrict__ A, const float* __restrict__ W1,
    const float* __restrict__ b1, const float* __restrict__ gam,
    const float* __restrict__ bet, const float* __restrict__ W2,
    const float* __restrict__ b2, float* __restrict__ Out)
{
    extern __shared__ float sm[];
    float* inter = sm;                     // 128 x 132
    float* bs   = sm + 128 * IS_STRIDE;
    float* gs   = bs + 128;
    float* bes  = gs + 128;
    float* b2s  = bes + 128;
    float* mus  = b2s + 128;
    float* invs = mus + 128;

    int tid = threadIdx.x;
    size_t n0 = (size_t)blockIdx.x * 128;

    if (tid < 128) {
        bs[tid]  = __ldg(&b1[tid]);
        gs[tid]  = __ldg(&gam[tid]);
        bes[tid] = __ldg(&bet[tid]);
        b2s[tid] = __ldg(&b2[tid]);
    }

    int wid = tid >> 5;
    int tr = wid >> 1, wc = wid & 1;

    wmma::fragment<wmma::accumulator, 16, 16, 8, float> acc[2][4];
#pragma unroll
    for (int i = 0; i < 2; i++)
#pragma unroll
        for (int j = 0; j < 4; j++) wmma::fill_fragment(acc[i][j], 0.0f);

    // GEMM1: A from global z (tf32), B from global W1 (tf32)
    do_gemm(A + n0 * DH, DH, W1, acc, tr, wc);

    // stage GEMM1 result into smem
#pragma unroll
    for (int i = 0; i < 2; i++)
#pragma unroll
        for (int j = 0; j < 4; j++)
            wmma::store_matrix_sync(inter + (tr * 32 + i * 16) * IS_STRIDE + wc * 64 + j * 16,
                                    acc[i][j], IS_STRIDE, wmma::mem_row_major);
    __syncthreads();

    // LN stats: 2 threads per row
    int row = tid >> 1, half = tid & 1;
    {
        const float* rp = inter + row * IS_STRIDE + half * 64;
        const float* bp = bs + half * 64;
        float s = 0.f, ss = 0.f;
#pragma unroll
        for (int c = 0; c < 64; c++) {
            float xv = rp[c] + bp[c];
            s += xv; ss += xv * xv;
        }
        s  += __shfl_xor_sync(0xffffffffu, s, 1);
        ss += __shfl_xor_sync(0xffffffffu, ss, 1);
        if (half == 0) {
            float mu = s * (1.0f / 128.0f);
            float var = ss * (1.0f / 128.0f) - mu * mu;
            mus[row] = mu;
            invs[row] = rsqrtf(var + LN_EPSF);
        }
    }
    __syncthreads();

    // normalize + relu in place (tf32 rounding for GEMM2)
    {
        float mu = mus[row], inv = invs[row];
        float* wrp = inter + row * IS_STRIDE + half * 64;
        const float* bp = bs + half * 64;
        const float* gp = gs + half * 64;
        const float* ep = bes + half * 64;
#pragma unroll
        for (int c = 0; c < 64; c++) {
            float xv = wrp[c] + bp[c];
            float y = (xv - mu) * inv * gp[c] + ep[c];
            wrp[c] = wmma::__float_to_tf32(fmaxf(y, 0.f));
        }
    }
    __syncthreads();

#pragma unroll
    for (int i = 0; i < 2; i++)
#pragma unroll
        for (int j = 0; j < 4; j++) wmma::fill_fragment(acc[i][j], 0.0f);

    // GEMM2: A from smem intermediate, B from global W2 (tf32)
    do_gemm(inter, IS_STRIDE, W2, acc, tr, wc);
    __syncthreads();

#pragma unroll
    for (int i = 0; i < 2; i++)
#pragma unroll
        for (int j = 0; j < 4; j++)
            wmma::store_matrix_sync(inter + (tr * 32 + i * 16) * IS_STRIDE + wc * 64 + j * 16,
                                    acc[i][j], IS_STRIDE, wmma::mem_row_major);
    __syncthreads();

    {
        float4* op = reinterpret_cast<float4*>(Out + n0 * DH);
        const float4* b4 = reinterpret_cast<const float4*>(b2s);
#pragma unroll
        for (int it = 0; it < 16; it++) {
            int i = tid + it * 256;
            int r = i >> 5, c = i & 31;
            float4 v = reinterpret_cast<float4*>(inter + r * IS_STRIDE)[c];
            float4 bv = b4[c];
            v.x += bv.x; v.y += bv.y; v.z += bv.z; v.w += bv.w;
            op[i] = v;
        }
    }
}

// ---------------- per-graph node sum ------------------------------------------
__global__ void sum_k(float* __restrict__ out, int off) {
    int g = blockIdx.x, d = threadIdx.x;
    const float* base = g_h + (size_t)g * NNODE * DH + d;
    float s = 0.f;
#pragma unroll 8
    for (int j = 0; j < NNODE; j++) s += base[(size_t)j * DH];
    out[g * 256 + off + d] = s;
}

// ---------------- launch ------------------------------------------------------
extern "C" void kernel_launch(void* const* d_in, const int* in_sizes, int n_in,
                              void* d_out, int out_size)
{
    const int*   x     = (const int*)d_in[0];
    const int*   ei    = (const int*)d_in[1];
    const int*   los   = (const int*)d_in[2];
    const float* emb   = (const float*)d_in[3];
    const float* lt    = (const float*)d_in[4];
    const float* g1w1  = (const float*)d_in[5];
    const float* g1b1  = (const float*)d_in[6];
    const float* g1g   = (const float*)d_in[7];
    const float* g1be  = (const float*)d_in[8];
    const float* g1w2  = (const float*)d_in[9];
    const float* g1b2  = (const float*)d_in[10];
    const float* g1eps = (const float*)d_in[11];
    const float* g2w1  = (const float*)d_in[12];
    const float* g2b1  = (const float*)d_in[13];
    const float* g2g   = (const float*)d_in[14];
    const float* g2be  = (const float*)d_in[15];
    const float* g2w2  = (const float*)d_in[16];
    const float* g2b2  = (const float*)d_in[17];
    const float* g2eps = (const float*)d_in[18];
    const float* g2ew  = (const float*)d_in[19];
    const float* g2eb  = (const float*)d_in[20];
    float* out = (float*)d_out;

    const int* src = ei;
    const int* dst = ei + EINT;

    void *ph, *pz, *pc, *pw;
    cudaGetSymbolAddress(&ph, g_h);
    cudaGetSymbolAddress(&pz, g_z);
    cudaGetSymbolAddress(&pc, g_cnt);
    cudaGetSymbolAddress(&pw, g_w);
    float* hB = (float*)ph;
    float* zB = (float*)pz;
    float* wB = (float*)pw;

    static int smem_set = 0;
    if (!smem_set) {
        cudaFuncSetAttribute(mlp_k, cudaFuncAttributeMaxDynamicSharedMemorySize,
                             MLP_SMEM_BYTES);
        smem_set = 1;
    }

    // weight pre-convert: order [g1w1L0, g1w2L0, g1w1L1, g1w2L1, g2w1L0, g2w2L0, g2w1L1, g2w2L1]
    convw_k<<<dim3(64, 8), 256>>>(
        g1w1, g1w2, g1w1 + DH * DH, g1w2 + DH * DH,
        g2w1, g2w2, g2w1 + DH * DH, g2w2 + DH * DH);

    embed_k<<<(NTOT * 32) / 256, 256>>>(x, emb);

    // CSR build
    cudaMemsetAsync(pc, 0, NTOT * sizeof(int));
    hist_k<<<EINT / 256, 256>>>(dst);
    scanA_k<<<NTOT / 256, 256>>>();
    scanB_k<<<1, 512>>>();
    scanC_k<<<NTOT / 256, 256>>>();
    fill_k<<<EINT / 256, 256>>>(src, dst);

    // ---- GIN layer group 1 ----
    for (int i = 0; i < 2; i++) {
        agg1_k<<<(NTOT * 32) / 256, 256>>>(g1eps + i);
        mlp_k<<<NTOT / 128, 256, MLP_SMEM_BYTES>>>(
            zB, wB + (size_t)(2 * i) * DH * DH, g1b1 + i * DH, g1g + i * DH,
            g1be + i * DH, wB + (size_t)(2 * i + 1) * DH * DH, g1b2 + i * DH, hB);
    }
    sum_k<<<2 * NB, DH>>>(out, 0);

    // ---- GINE layer group 2 ----
    for (int i = 0; i < 2; i++) {
        table_k<<<38, DH>>>(lt, g2ew + (size_t)i * 8 * DH, g2eb + i * DH);
        agg2_k<<<(NTOT * 32) / 256, 256>>>(g2eps + i, los);
        mlp_k<<<NTOT / 128, 256, MLP_SMEM_BYTES>>>(
            zB, wB + (size_t)(4 + 2 * i) * DH * DH, g2b1 + i * DH, g2g + i * DH,
            g2be + i * DH, wB + (size_t)(5 + 2 * i) * DH * DH, g2b2 + i * DH, hB);
    }
    sum_k<<<2 * NB, DH>>>(out, 128);
}